// round 1
// baseline (speedup 1.0000x reference)
#include <cuda_runtime.h>

// ---------------------------------------------------------------------------
// DifferentiablePhysicsEngine energy on GB300.
// Shapes: coords (8,512,4,3) f32, motors (8,512,8) f32, mask (8,512) f32.
// Output: scalar f32.
//
// Structure:
//   kernel 1 (role-dispatch, 1128 blocks x 128 thr):
//     [0,1088)      : LJ all-pairs, triangular tile pairs (16 tiles of 128 per
//                     batch -> 136 tile-pairs x 8 batches). Block partial sums.
//     [1088,1120)   : HB N-vs-O 512x512 per batch, 4 i-tiles x 8 batches.
//     [1120,1128)   : per-batch stats (mask sums, CA moments, motor smoothness).
//   kernel 2: deterministic fixed-order reduction + final scalar combine.
// No atomics -> bit-deterministic across replays.
// ---------------------------------------------------------------------------

static constexpr int Bsz  = 8;
static constexpr int Ssz  = 512;
static constexpr int NF   = Ssz * 4;            // 2048 flat atoms
static constexpr int TPB  = 128;
static constexpr int TILE = 128;
static constexpr int NT   = NF / TILE;          // 16
static constexpr int NPAIR = NT * (NT + 1) / 2; // 136
static constexpr int LJ_BLOCKS   = Bsz * NPAIR; // 1088
static constexpr int HB_TI       = Ssz / TILE;  // 4
static constexpr int HB_BLOCKS   = Bsz * HB_TI; // 32
static constexpr int STAT_BLOCKS = Bsz;         // 8
static constexpr int TOTAL_BLOCKS = LJ_BLOCKS + HB_BLOCKS + STAT_BLOCKS;

// scratch (no device allocation allowed -> __device__ globals)
__device__ float g_lj[LJ_BLOCKS];
__device__ float g_hb[HB_BLOCKS];
__device__ float g_stats[Bsz][8]; // msum, msum2, s1x, s1y, s1z, s2, motor, mmask

__device__ __forceinline__ float fsqrt_ap(float x) {
    float r; asm("sqrt.approx.f32 %0, %1;" : "=f"(r) : "f"(x)); return r;
}
__device__ __forceinline__ float fex2_ap(float x) {
    float r; asm("ex2.approx.f32 %0, %1;" : "=f"(r) : "f"(x)); return r;
}

__device__ __forceinline__ float block_reduce(float v, float* red) {
    int t = threadIdx.x;
    red[t] = v;
    __syncthreads();
#pragma unroll
    for (int off = TPB / 2; off > 0; off >>= 1) {
        if (t < off) red[t] += red[t + off];
        __syncthreads();
    }
    float r = red[0];
    __syncthreads();
    return r;
}

#define LJ_PAIR(xj, yj, zj, mj)                                        \
    do {                                                               \
        float dx = xi - (xj), dy = yi - (yj), dz = zi - (zj);          \
        float d2 = fmaf(dx, dx, fmaf(dy, dy, fmaf(dz, dz, 1e-6f)));    \
        float r  = fsqrt_ap(d2);                                       \
        float ov = fmaxf(3.0f - r, 0.0f);                              \
        float ov2 = ov * ov;                                           \
        acc = fmaf(ov2 * ov2, (mj), acc);                              \
    } while (0)

#define HB_PAIR(xj, yj, zj, mj, jg)                                    \
    do {                                                               \
        float dx = xi - (xj), dy = yi - (yj), dz = zi - (zj);          \
        float d2 = fmaf(dx, dx, fmaf(dy, dy, dz * dz));                \
        float r  = fsqrt_ap(d2);                                       \
        float d  = r - 2.9f;                                           \
        float e  = fex2_ap(d * d * (-18.033688011112043f));            \
        int  dj  = (jg) - i;                                           \
        if (dj > 2 || dj < -2) acc = fmaf(e, (mj), acc);               \
    } while (0)

__global__ __launch_bounds__(TPB)
void energy_main(const float* __restrict__ coords,
                 const float* __restrict__ motors,
                 const float* __restrict__ mask) {
    __shared__ alignas(16) float smem[4 * Ssz]; // 8 KB, role-dependent layout
    __shared__ float red[TPB];
    const int blk = blockIdx.x;
    const int t   = threadIdx.x;

    if (blk < LJ_BLOCKS) {
        // ----------------------- LJ clash term -----------------------------
        const int b = blk / NPAIR;
        int p = blk % NPAIR;
        int bi = 0;
        while (p >= NT - bi) { p -= NT - bi; ++bi; }
        const int bj = bi + p;

        const float* cb = coords + (size_t)b * NF * 3;
        const float* mb = mask + (size_t)b * Ssz;
        float* sx = smem;            float* sy = smem + TILE;
        float* sz = smem + 2 * TILE; float* sm = smem + 3 * TILE;

        const int jr = bj * TILE + t;
        sx[t] = cb[jr * 3 + 0];
        sy[t] = cb[jr * 3 + 1];
        sz[t] = cb[jr * 3 + 2];
        sm[t] = mb[jr >> 2];

        const int ig = bi * TILE + t;
        const float xi = cb[ig * 3 + 0];
        const float yi = cb[ig * 3 + 1];
        const float zi = cb[ig * 3 + 2];
        const float mi = mb[ig >> 2];
        __syncthreads();

        float acc = 0.0f;
        if (bi != bj) {
            const float4* X4 = (const float4*)sx;
            const float4* Y4 = (const float4*)sy;
            const float4* Z4 = (const float4*)sz;
            const float4* M4 = (const float4*)sm;
#pragma unroll 4
            for (int g = 0; g < TILE / 4; ++g) {
                float4 x = X4[g], y = Y4[g], z = Z4[g], m = M4[g];
                LJ_PAIR(x.x, y.x, z.x, m.x);
                LJ_PAIR(x.y, y.y, z.y, m.y);
                LJ_PAIR(x.z, y.z, z.z, m.z);
                LJ_PAIR(x.w, y.w, z.w, m.w);
            }
        } else {
            // strict upper triangle within the tile (j > i)
            for (int l = t + 1; l < TILE; ++l) {
                LJ_PAIR(sx[l], sy[l], sz[l], sm[l]);
            }
        }
        float v = block_reduce(acc * mi, red);
        if (t == 0) g_lj[blk] = v;

    } else if (blk < LJ_BLOCKS + HB_BLOCKS) {
        // --------------------- hydrogen-bond term --------------------------
        const int q  = blk - LJ_BLOCKS;
        const int b  = q / HB_TI;
        const int it = q % HB_TI;
        const float* cb = coords + (size_t)b * NF * 3;
        const float* mb = mask + (size_t)b * Ssz;
        float* ox = smem;           float* oy = smem + Ssz;
        float* oz = smem + 2 * Ssz; float* om = smem + 3 * Ssz;

        for (int j = t; j < Ssz; j += TPB) {
            const float* row = cb + (j * 4 + 3) * 3; // O atom
            ox[j] = row[0]; oy[j] = row[1]; oz[j] = row[2];
            om[j] = mb[j];
        }
        const int i = it * TILE + t;
        const float* nr = cb + i * 12; // N atom
        const float xi = nr[0], yi = nr[1], zi = nr[2];
        const float mi = mb[i];
        __syncthreads();

        float acc = 0.0f;
        const float4* X4 = (const float4*)ox;
        const float4* Y4 = (const float4*)oy;
        const float4* Z4 = (const float4*)oz;
        const float4* M4 = (const float4*)om;
#pragma unroll 4
        for (int g = 0; g < Ssz / 4; ++g) {
            float4 x = X4[g], y = Y4[g], z = Z4[g], m = M4[g];
            const int j0 = 4 * g;
            HB_PAIR(x.x, y.x, z.x, m.x, j0 + 0);
            HB_PAIR(x.y, y.y, z.y, m.y, j0 + 1);
            HB_PAIR(x.z, y.z, z.z, m.z, j0 + 2);
            HB_PAIR(x.w, y.w, z.w, m.w, j0 + 3);
        }
        float v = block_reduce(acc * mi, red);
        if (t == 0) g_hb[q] = v;

    } else {
        // ------------- per-batch stats: mask sums, CA moments, motor --------
        const int b = blk - LJ_BLOCKS - HB_BLOCKS;
        const float* cb = coords + (size_t)b * NF * 3;
        const float* mb = mask + (size_t)b * Ssz;
        const float* mo = motors + (size_t)b * Ssz * 8;

        float msum = 0.f, msum2 = 0.f;
        float s1x = 0.f, s1y = 0.f, s1z = 0.f, s2 = 0.f;
        float mot = 0.f, mm = 0.f;

        for (int s = t; s < Ssz; s += TPB) {
            const float m = mb[s];
            msum += m;
            msum2 = fmaf(m, m, msum2);
            const float* ca = cb + (s * 4 + 1) * 3;
            const float cx = ca[0], cy = ca[1], cz = ca[2];
            s1x = fmaf(cx, m, s1x);
            s1y = fmaf(cy, m, s1y);
            s1z = fmaf(cz, m, s1z);
            s2  = fmaf(fmaf(cx, cx, fmaf(cy, cy, cz * cz)), m, s2);
            if (s < Ssz - 1) {
                const float mn = mb[s + 1];
                const float4* r4 = (const float4*)(mo + s * 8);
                float4 a0 = r4[0], a1 = r4[1], b0 = r4[2], b1 = r4[3];
                float d, ds = 0.f;
                d = b0.x - a0.x; ds = fmaf(d, d, ds);
                d = b0.y - a0.y; ds = fmaf(d, d, ds);
                d = b0.z - a0.z; ds = fmaf(d, d, ds);
                d = b0.w - a0.w; ds = fmaf(d, d, ds);
                d = b1.x - a1.x; ds = fmaf(d, d, ds);
                d = b1.y - a1.y; ds = fmaf(d, d, ds);
                d = b1.z - a1.z; ds = fmaf(d, d, ds);
                d = b1.w - a1.w; ds = fmaf(d, d, ds);
                mot = fmaf(ds, m * mn, mot);
                mm  = fmaf(m, mn, mm);
            }
        }
        float vals[8] = {msum, msum2, s1x, s1y, s1z, s2, mot, mm};
#pragma unroll
        for (int k = 0; k < 8; ++k) {
            float v = block_reduce(vals[k], red);
            if (t == 0) g_stats[b][k] = v;
        }
    }
}

__global__ __launch_bounds__(256)
void energy_combine(float* __restrict__ out) {
    __shared__ float red[256];
    const int t = threadIdx.x;

    float a = 0.f;
    for (int i = t; i < LJ_BLOCKS; i += 256) a += g_lj[i];
    red[t] = a; __syncthreads();
#pragma unroll
    for (int off = 128; off > 0; off >>= 1) {
        if (t < off) red[t] += red[t + off];
        __syncthreads();
    }
    const float S_lj = red[0]; __syncthreads();

    float h = (t < HB_BLOCKS) ? g_hb[t] : 0.f;
    red[t] = h; __syncthreads();
#pragma unroll
    for (int off = 128; off > 0; off >>= 1) {
        if (t < off) red[t] += red[t + off];
        __syncthreads();
    }
    const float S_hb = red[0]; __syncthreads();

    if (t == 0) {
        double P = 0.0, Mtot = 0.0, Smot = 0.0, Smm = 0.0, rg = 0.0;
        for (int b = 0; b < Bsz; ++b) {
            const double ms  = g_stats[b][0];
            const double ms2 = g_stats[b][1];
            P    += 16.0 * ms * ms - 4.0 * ms2;
            Mtot += ms;
            Smot += g_stats[b][6];
            Smm  += g_stats[b][7];
            const double den = ms + 1e-6;
            const double S1x = g_stats[b][2], S1y = g_stats[b][3], S1z = g_stats[b][4];
            const double s2  = g_stats[b][5];
            const double ux = S1x / den, uy = S1y / den, uz = S1z / den;
            const double dot = ux * S1x + uy * S1y + uz * S1z;
            const double u2  = ux * ux + uy * uy + uz * uz;
            rg += (s2 - 2.0 * dot + u2 * ms) / den;
        }
        rg /= (double)Bsz;
        const double lj    = 2.0 * (double)S_lj / (P + 1e-6);
        const double hb    = -(double)S_hb / (Mtot + 1e-6);
        const double motor = Smot / (Smm + 1e-6);
        out[0] = (float)(lj + 0.5 * hb + 0.1 * motor + 0.05 * rg);
    }
}

extern "C" void kernel_launch(void* const* d_in, const int* in_sizes, int n_in,
                              void* d_out, int out_size) {
    // Identify inputs by element count (robust to metadata order):
    // coords = 8*512*4*3 = 49152, motors = 8*512*8 = 32768, mask = 8*512 = 4096
    const float* coords = nullptr;
    const float* motors = nullptr;
    const float* mask   = nullptr;
    for (int i = 0; i < n_in; ++i) {
        if (in_sizes[i] == Bsz * Ssz * 4 * 3)      coords = (const float*)d_in[i];
        else if (in_sizes[i] == Bsz * Ssz * 8)     motors = (const float*)d_in[i];
        else if (in_sizes[i] == Bsz * Ssz)         mask   = (const float*)d_in[i];
    }
    float* out = (float*)d_out;
    energy_main<<<TOTAL_BLOCKS, TPB>>>(coords, motors, mask);
    energy_combine<<<1, 256>>>(out);
}

// round 2
// speedup vs baseline: 2.2956x; 2.2956x over previous
#include <cuda_runtime.h>

// ---------------------------------------------------------------------------
// DifferentiablePhysicsEngine energy on GB300 — single fused kernel.
//   [0,1088)      LJ all-pairs, triangular tile pairs, f32x2-packed inner loop
//   [1088,1216)   HB N-vs-O, 8 batches x 4 i-tiles x 4 j-chunks
//   [1216,1224)   per-batch stats (mask sums, CA moments, motor smoothness)
// Last-arriving block (atomic ticket) performs the fixed-order final combine
// in float and writes the scalar. No second launch, no DP divides.
// ---------------------------------------------------------------------------

static constexpr int Bsz  = 8;
static constexpr int Ssz  = 512;
static constexpr int NF   = Ssz * 4;            // 2048 flat atoms
static constexpr int TPB  = 128;
static constexpr int TILE = 128;
static constexpr int NT   = NF / TILE;          // 16
static constexpr int NPAIR = NT * (NT + 1) / 2; // 136
static constexpr int LJ_BLOCKS = Bsz * NPAIR;   // 1088
static constexpr int HB_IT = 4, HB_JC = 4;
static constexpr int HB_BLOCKS = Bsz * HB_IT * HB_JC; // 128
static constexpr int STAT_BLOCKS = Bsz;               // 8
static constexpr int TOTAL_BLOCKS = LJ_BLOCKS + HB_BLOCKS + STAT_BLOCKS; // 1224

__device__ float g_lj[LJ_BLOCKS];
__device__ float g_hb[HB_BLOCKS];
__device__ float g_stats[Bsz][8]; // msum, msum2, s1x, s1y, s1z, s2, motor, mmask
__device__ unsigned int g_count = 0;

// ---------------- f32x2 helpers (Blackwell packed fp32) --------------------
typedef unsigned long long u64;

__device__ __forceinline__ u64 pk2(float lo, float hi) {
    u64 r; asm("mov.b64 %0, {%1,%2};" : "=l"(r) : "f"(lo), "f"(hi)); return r;
}
__device__ __forceinline__ void unpk2(u64 p, float& lo, float& hi) {
    asm("mov.b64 {%0,%1}, %2;" : "=f"(lo), "=f"(hi) : "l"(p));
}
__device__ __forceinline__ u64 addx2(u64 a, u64 b) {
    u64 d; asm("add.rn.f32x2 %0, %1, %2;" : "=l"(d) : "l"(a), "l"(b)); return d;
}
__device__ __forceinline__ u64 mulx2(u64 a, u64 b) {
    u64 d; asm("mul.rn.f32x2 %0, %1, %2;" : "=l"(d) : "l"(a), "l"(b)); return d;
}
__device__ __forceinline__ u64 fmax2(u64 a, u64 b, u64 c) {
    u64 d; asm("fma.rn.f32x2 %0, %1, %2, %3;" : "=l"(d) : "l"(a), "l"(b), "l"(c)); return d;
}
__device__ __forceinline__ float fsqrt_ap(float x) {
    float r; asm("sqrt.approx.f32 %0, %1;" : "=f"(r) : "f"(x)); return r;
}
__device__ __forceinline__ float fex2_ap(float x) {
    float r; asm("ex2.approx.f32 %0, %1;" : "=f"(r) : "f"(x)); return r;
}

static constexpr u64 EPS_P = 0x358637BD358637BDull; // {1e-6f, 1e-6f}

__device__ __forceinline__ float block_reduce(float v, float* red) {
    int t = threadIdx.x;
    red[t] = v;
    __syncthreads();
#pragma unroll
    for (int off = TPB / 2; off > 0; off >>= 1) {
        if (t < off) red[t] += red[t + off];
        __syncthreads();
    }
    float r = red[0];
    __syncthreads();
    return r;
}

// 2 LJ pairs: nx/ny/nz hold NEGATED j coords packed, m holds masks packed.
#define LJ2(nx, ny, nz, mp, acc)                                        \
    do {                                                                \
        u64 dX = addx2(xip, (nx));                                      \
        u64 dY = addx2(yip, (ny));                                      \
        u64 dZ = addx2(zip, (nz));                                      \
        u64 d2 = fmax2(dZ, dZ, EPS_P);                                  \
        d2 = fmax2(dY, dY, d2);                                         \
        d2 = fmax2(dX, dX, d2);                                         \
        float d2a, d2b; unpk2(d2, d2a, d2b);                            \
        float ra = fsqrt_ap(d2a), rb = fsqrt_ap(d2b);                   \
        float sa = fmaxf(__fmaf_rn(ra, -1.0f, 3.0f), 0.0f);             \
        float sb = fmaxf(__fmaf_rn(rb, -1.0f, 3.0f), 0.0f);             \
        u64 ov  = pk2(sa, sb);                                          \
        u64 ov2 = mulx2(ov, ov);                                        \
        u64 ov4 = mulx2(ov2, ov2);                                      \
        acc = fmax2(ov4, (mp), acc);                                    \
    } while (0)

#define LJ_PAIR_S(nxj, nyj, nzj, mj)                                    \
    do {                                                                \
        float dx = xi + (nxj), dy = yi + (nyj), dz = zi + (nzj);        \
        float d2 = fmaf(dx, dx, fmaf(dy, dy, fmaf(dz, dz, 1e-6f)));     \
        float r  = fsqrt_ap(d2);                                        \
        float ov = fmaxf(__fmaf_rn(r, -1.0f, 3.0f), 0.0f);              \
        float ov2 = ov * ov;                                            \
        accS = fmaf(ov2 * ov2, (mj), accS);                             \
    } while (0)

#define HB_PAIR(xj, yj, zj, mj, jg)                                     \
    do {                                                                \
        float dx = xi - (xj), dy = yi - (yj), dz = zi - (zj);           \
        float d2 = fmaf(dx, dx, fmaf(dy, dy, dz * dz));                 \
        float r  = fsqrt_ap(d2);                                        \
        float d  = __fmaf_rn(r, -1.0f, 2.9f);                           \
        float e  = fex2_ap(d * d * (-18.033688011112043f));             \
        int  dj  = (jg) - i;                                            \
        if (dj > 2 || dj < -2) acc = fmaf(e, (mj), acc);                \
    } while (0)

__global__ __launch_bounds__(TPB)
void energy_fused(const float* __restrict__ coords,
                  const float* __restrict__ motors,
                  const float* __restrict__ mask,
                  float* __restrict__ out) {
    __shared__ alignas(16) float smem[4 * TILE]; // 2 KB role-dependent
    __shared__ float red[TPB];
    __shared__ int s_last;
    const int blk = blockIdx.x;
    const int t   = threadIdx.x;

    if (blk < LJ_BLOCKS) {
        // ----------------------- LJ clash term -----------------------------
        const int b = blk / NPAIR;
        int p = blk % NPAIR;
        int bi = 0;
        while (p >= NT - bi) { p -= NT - bi; ++bi; }
        const int bj = bi + p;

        const float* cb = coords + (size_t)b * NF * 3;
        const float* mb = mask + (size_t)b * Ssz;
        float* snx = smem;            float* sny = smem + TILE;
        float* snz = smem + 2 * TILE; float* sm  = smem + 3 * TILE;

        const int jr = bj * TILE + t;
        snx[t] = -cb[jr * 3 + 0];
        sny[t] = -cb[jr * 3 + 1];
        snz[t] = -cb[jr * 3 + 2];
        sm[t]  =  mb[jr >> 2];

        const int ig = bi * TILE + t;
        const float xi = cb[ig * 3 + 0];
        const float yi = cb[ig * 3 + 1];
        const float zi = cb[ig * 3 + 2];
        const float mi = mb[ig >> 2];
        __syncthreads();

        float total = 0.0f;
        if (bi != bj) {
            const u64 xip = pk2(xi, xi), yip = pk2(yi, yi), zip = pk2(zi, zi);
            const ulonglong2* NX = (const ulonglong2*)snx;
            const ulonglong2* NY = (const ulonglong2*)sny;
            const ulonglong2* NZ = (const ulonglong2*)snz;
            const ulonglong2* MM = (const ulonglong2*)sm;
            u64 accA = 0ull, accB = 0ull; // packed {0,0}
#pragma unroll 8
            for (int g = 0; g < TILE / 4; ++g) {
                ulonglong2 X = NX[g], Y = NY[g], Z = NZ[g], M = MM[g];
                LJ2(X.x, Y.x, Z.x, M.x, accA);
                LJ2(X.y, Y.y, Z.y, M.y, accB);
            }
            float a0, a1, b0, b1;
            unpk2(accA, a0, a1);
            unpk2(accB, b0, b1);
            total = (a0 + a1) + (b0 + b1);
        } else {
            float accS = 0.0f;
            for (int l = t + 1; l < TILE; ++l) {
                LJ_PAIR_S(snx[l], sny[l], snz[l], sm[l]);
            }
            total = accS;
        }
        float v = block_reduce(total * mi, red);
        if (t == 0) g_lj[blk] = v;

    } else if (blk < LJ_BLOCKS + HB_BLOCKS) {
        // --------------------- hydrogen-bond term --------------------------
        const int q  = blk - LJ_BLOCKS;
        const int b  = q / (HB_IT * HB_JC);
        const int rr = q % (HB_IT * HB_JC);
        const int it = rr / HB_JC;
        const int jc = rr % HB_JC;
        const float* cb = coords + (size_t)b * NF * 3;
        const float* mb = mask + (size_t)b * Ssz;
        float* ox = smem;            float* oy = smem + TILE;
        float* oz = smem + 2 * TILE; float* om = smem + 3 * TILE;

        const int j0 = jc * TILE;
        {
            const float* row = cb + ((j0 + t) * 4 + 3) * 3; // O atom
            ox[t] = row[0]; oy[t] = row[1]; oz[t] = row[2];
            om[t] = mb[j0 + t];
        }
        const int i = it * TILE + t;
        const float* nr = cb + i * 12; // N atom
        const float xi = nr[0], yi = nr[1], zi = nr[2];
        const float mi = mb[i];
        __syncthreads();

        float acc = 0.0f;
        const float4* X4 = (const float4*)ox;
        const float4* Y4 = (const float4*)oy;
        const float4* Z4 = (const float4*)oz;
        const float4* M4 = (const float4*)om;
#pragma unroll 4
        for (int g = 0; g < TILE / 4; ++g) {
            float4 x = X4[g], y = Y4[g], z = Z4[g], m = M4[g];
            const int jb = j0 + 4 * g;
            HB_PAIR(x.x, y.x, z.x, m.x, jb + 0);
            HB_PAIR(x.y, y.y, z.y, m.y, jb + 1);
            HB_PAIR(x.z, y.z, z.z, m.z, jb + 2);
            HB_PAIR(x.w, y.w, z.w, m.w, jb + 3);
        }
        float v = block_reduce(acc * mi, red);
        if (t == 0) g_hb[q] = v;

    } else {
        // ------------- per-batch stats: mask sums, CA moments, motor --------
        const int b = blk - LJ_BLOCKS - HB_BLOCKS;
        const float* cb = coords + (size_t)b * NF * 3;
        const float* mb = mask + (size_t)b * Ssz;
        const float* mo = motors + (size_t)b * Ssz * 8;

        float msum = 0.f, msum2 = 0.f;
        float s1x = 0.f, s1y = 0.f, s1z = 0.f, s2 = 0.f;
        float mot = 0.f, mm = 0.f;

        for (int s = t; s < Ssz; s += TPB) {
            const float m = mb[s];
            msum += m;
            msum2 = fmaf(m, m, msum2);
            const float* ca = cb + (s * 4 + 1) * 3;
            const float cx = ca[0], cy = ca[1], cz = ca[2];
            s1x = fmaf(cx, m, s1x);
            s1y = fmaf(cy, m, s1y);
            s1z = fmaf(cz, m, s1z);
            s2  = fmaf(fmaf(cx, cx, fmaf(cy, cy, cz * cz)), m, s2);
            if (s < Ssz - 1) {
                const float mn = mb[s + 1];
                const float4* r4 = (const float4*)(mo + s * 8);
                float4 a0 = r4[0], a1 = r4[1], b0 = r4[2], b1 = r4[3];
                float d, ds = 0.f;
                d = b0.x - a0.x; ds = fmaf(d, d, ds);
                d = b0.y - a0.y; ds = fmaf(d, d, ds);
                d = b0.z - a0.z; ds = fmaf(d, d, ds);
                d = b0.w - a0.w; ds = fmaf(d, d, ds);
                d = b1.x - a1.x; ds = fmaf(d, d, ds);
                d = b1.y - a1.y; ds = fmaf(d, d, ds);
                d = b1.z - a1.z; ds = fmaf(d, d, ds);
                d = b1.w - a1.w; ds = fmaf(d, d, ds);
                mot = fmaf(ds, m * mn, mot);
                mm  = fmaf(m, mn, mm);
            }
        }
        float vals[8] = {msum, msum2, s1x, s1y, s1z, s2, mot, mm};
#pragma unroll
        for (int k = 0; k < 8; ++k) {
            float v = block_reduce(vals[k], red);
            if (t == 0) g_stats[b][k] = v;
        }
    }

    // ------------------- last-block final combine (fixed order) ------------
    __syncthreads();
    if (t == 0) {
        __threadfence();
        unsigned int old = atomicAdd(&g_count, 1u);
        s_last = (old == (unsigned int)(TOTAL_BLOCKS - 1)) ? 1 : 0;
    }
    __syncthreads();
    if (!s_last) return;

    __threadfence();
    float a = 0.f;
    for (int idx = t; idx < LJ_BLOCKS; idx += TPB) a += __ldcg(&g_lj[idx]);
    const float S_lj = block_reduce(a, red);

    float h = (t < HB_BLOCKS) ? __ldcg(&g_hb[t]) : 0.f;
    const float S_hb = block_reduce(h, red);

    if (t == 0) {
        float P = 0.f, Mtot = 0.f, Smot = 0.f, Smm = 0.f, rg = 0.f;
#pragma unroll
        for (int b = 0; b < Bsz; ++b) {
            float st[8];
#pragma unroll
            for (int k = 0; k < 8; ++k) st[k] = __ldcg(&g_stats[b][k]);
            const float ms = st[0], ms2 = st[1];
            P    = fmaf(16.f * ms, ms, P) - 4.f * ms2;
            Mtot += ms;
            Smot += st[6];
            Smm  += st[7];
            const float den = ms + 1e-6f;
            const float inv = __fdividef(1.0f, den);
            const float ux = st[2] * inv, uy = st[3] * inv, uz = st[4] * inv;
            const float dot = ux * st[2] + uy * st[3] + uz * st[4];
            const float u2  = ux * ux + uy * uy + uz * uz;
            rg += (st[5] - 2.f * dot + u2 * ms) * inv;
        }
        rg *= (1.0f / (float)Bsz);
        const float lj    = 2.0f * S_lj * __fdividef(1.0f, P + 1e-6f);
        const float hb    = -S_hb * __fdividef(1.0f, Mtot + 1e-6f);
        const float motor = Smot * __fdividef(1.0f, Smm + 1e-6f);
        out[0] = lj + 0.5f * hb + 0.1f * motor + 0.05f * rg;
        g_count = 0; // reset for next graph replay
    }
}

extern "C" void kernel_launch(void* const* d_in, const int* in_sizes, int n_in,
                              void* d_out, int out_size) {
    const float* coords = nullptr;
    const float* motors = nullptr;
    const float* mask   = nullptr;
    for (int i = 0; i < n_in; ++i) {
        if (in_sizes[i] == Bsz * Ssz * 4 * 3)   coords = (const float*)d_in[i];
        else if (in_sizes[i] == Bsz * Ssz * 8)  motors = (const float*)d_in[i];
        else if (in_sizes[i] == Bsz * Ssz)      mask   = (const float*)d_in[i];
    }
    energy_fused<<<TOTAL_BLOCKS, TPB>>>(coords, motors, mask, (float*)d_out);
}